// round 3
// baseline (speedup 1.0000x reference)
#include <cuda_runtime.h>
#include <math.h>

// Shapes (fixed for this problem)
#define QL 1024
#define CL 2048
#define BATCH 16
#define DIM 1024

#define BM 128
#define BN 128
#define BK 8
#define PAD 132   // padded smem row (in floats): conflict-free + 16B-aligned rows

// Scratch: qb and ctx, [b, q, dim] each = 64 MB
__device__ float g_qb [(size_t)BATCH * QL * DIM];
__device__ float g_ctx[(size_t)BATCH * QL * DIM];

// ---------------------------------------------------------------------------
// C = A * B^T  (A: M x K, K-contiguous with row stride lda;
//               B: N x K, K-contiguous with row stride ldb)
// Optional: CONCAT (A is [A0 | A1] along K, split at Ksplit), TANH epilogue.
// Tiles: 128x128x8, 256 threads, 8x8 per-thread register tile.
// ---------------------------------------------------------------------------
template<bool TANH, bool CONCAT>
__global__ __launch_bounds__(256, 2)
void gemm_tt_kernel(const float* __restrict__ A0, const float* __restrict__ A1,
                    long lda, long sAb,
                    const float* __restrict__ B, long ldb, long sBb,
                    float* __restrict__ C, long ldc, long sCb,
                    int K, int Ksplit)
{
    __shared__ float As[BK][PAD];
    __shared__ float Bs[BK][PAD];

    const int bi = blockIdx.z;
    const float* Ab0 = A0 + (long)bi * sAb;
    const float* Ab1 = CONCAT ? (A1 + (long)bi * sAb) : Ab0;
    const float* Bb  = B  + (long)bi * sBb;
    float*       Cb  = C  + (long)bi * sCb;

    const int m0 = blockIdx.y * BM;
    const int n0 = blockIdx.x * BN;
    const int tid  = threadIdx.x;
    const int lrow = tid >> 1;          // 0..127: tile row for global loads
    const int lk   = (tid & 1) * 4;     // 0 or 4: k offset for global loads
    const int tx   = tid & 15;
    const int ty   = tid >> 4;

    float acc[8][8];
    #pragma unroll
    for (int i = 0; i < 8; i++)
        #pragma unroll
        for (int j = 0; j < 8; j++) acc[i][j] = 0.f;

    for (int k0 = 0; k0 < K; k0 += BK) {
        const float* Aptr;
        int ka;
        if (CONCAT && k0 >= Ksplit) { Aptr = Ab1; ka = k0 - Ksplit; }
        else                        { Aptr = Ab0; ka = k0; }

        float4 av = *(const float4*)(Aptr + (long)(m0 + lrow) * lda + ka + lk);
        float4 bv = *(const float4*)(Bb   + (long)(n0 + lrow) * ldb + k0 + lk);

        __syncthreads();
        As[lk + 0][lrow] = av.x; As[lk + 1][lrow] = av.y;
        As[lk + 2][lrow] = av.z; As[lk + 3][lrow] = av.w;
        Bs[lk + 0][lrow] = bv.x; Bs[lk + 1][lrow] = bv.y;
        Bs[lk + 2][lrow] = bv.z; Bs[lk + 3][lrow] = bv.w;
        __syncthreads();

        #pragma unroll
        for (int kk = 0; kk < BK; kk++) {
            float a[8], b8[8];
            *(float4*)(a)     = *(const float4*)&As[kk][ty * 8];
            *(float4*)(a + 4) = *(const float4*)&As[kk][ty * 8 + 4];
            *(float4*)(b8)     = *(const float4*)&Bs[kk][tx * 8];
            *(float4*)(b8 + 4) = *(const float4*)&Bs[kk][tx * 8 + 4];
            #pragma unroll
            for (int i = 0; i < 8; i++)
                #pragma unroll
                for (int j = 0; j < 8; j++)
                    acc[i][j] += a[i] * b8[j];
        }
    }

    #pragma unroll
    for (int i = 0; i < 8; i++) {
        long rbase = (long)(m0 + ty * 8 + i) * ldc + n0 + tx * 8;
        #pragma unroll
        for (int j = 0; j < 8; j += 4) {
            float4 o;
            o.x = TANH ? tanhf(acc[i][j + 0]) : acc[i][j + 0];
            o.y = TANH ? tanhf(acc[i][j + 1]) : acc[i][j + 1];
            o.z = TANH ? tanhf(acc[i][j + 2]) : acc[i][j + 2];
            o.w = TANH ? tanhf(acc[i][j + 3]) : acc[i][j + 3];
            *(float4*)(Cb + rbase + j) = o;
        }
    }
}

// ---------------------------------------------------------------------------
// C = A * B  (A: M x K, K-contiguous, row stride lda;
//             B: K x N, N-contiguous, row stride ldb)
// ---------------------------------------------------------------------------
__global__ __launch_bounds__(256, 2)
void gemm_tn_kernel(const float* __restrict__ A, long lda, long sAb,
                    const float* __restrict__ B, long ldb, long sBb,
                    float* __restrict__ C, long ldc, long sCb, int K)
{
    __shared__ float As[BK][PAD];
    __shared__ float Bs[BK][PAD];

    const int bi = blockIdx.z;
    const float* Ab = A + (long)bi * sAb;
    const float* Bb = B + (long)bi * sBb;
    float*       Cb = C + (long)bi * sCb;

    const int m0 = blockIdx.y * BM;
    const int n0 = blockIdx.x * BN;
    const int tid  = threadIdx.x;
    const int lrow = tid >> 1;
    const int lk   = (tid & 1) * 4;
    const int brow = tid >> 5;          // 0..7: B tile k-row
    const int bcol = (tid & 31) * 4;    // 0..124
    const int tx   = tid & 15;
    const int ty   = tid >> 4;

    float acc[8][8];
    #pragma unroll
    for (int i = 0; i < 8; i++)
        #pragma unroll
        for (int j = 0; j < 8; j++) acc[i][j] = 0.f;

    for (int k0 = 0; k0 < K; k0 += BK) {
        float4 av = *(const float4*)(Ab + (long)(m0 + lrow) * lda + k0 + lk);
        float4 bv = *(const float4*)(Bb + (long)(k0 + brow) * ldb + n0 + bcol);

        __syncthreads();
        As[lk + 0][lrow] = av.x; As[lk + 1][lrow] = av.y;
        As[lk + 2][lrow] = av.z; As[lk + 3][lrow] = av.w;
        *(float4*)&Bs[brow][bcol] = bv;
        __syncthreads();

        #pragma unroll
        for (int kk = 0; kk < BK; kk++) {
            float a[8], b8[8];
            *(float4*)(a)     = *(const float4*)&As[kk][ty * 8];
            *(float4*)(a + 4) = *(const float4*)&As[kk][ty * 8 + 4];
            *(float4*)(b8)     = *(const float4*)&Bs[kk][tx * 8];
            *(float4*)(b8 + 4) = *(const float4*)&Bs[kk][tx * 8 + 4];
            #pragma unroll
            for (int i = 0; i < 8; i++)
                #pragma unroll
                for (int j = 0; j < 8; j++)
                    acc[i][j] += a[i] * b8[j];
        }
    }

    #pragma unroll
    for (int i = 0; i < 8; i++) {
        long rbase = (long)(m0 + ty * 8 + i) * ldc + n0 + tx * 8;
        #pragma unroll
        for (int j = 0; j < 8; j += 4) {
            float4 o;
            o.x = acc[i][j + 0]; o.y = acc[i][j + 1];
            o.z = acc[i][j + 2]; o.w = acc[i][j + 3];
            *(float4*)(Cb + rbase + j) = o;
        }
    }
}

// ---------------------------------------------------------------------------
// In-place softmax over rows of 2048 (one block per row, 256 threads x 8 elems)
// ---------------------------------------------------------------------------
__global__ __launch_bounds__(256)
void softmax2048_kernel(float* __restrict__ S)
{
    float* row = S + (long)blockIdx.x * 2048;
    const int t = threadIdx.x;
    __shared__ float sred[8];

    float v[8];
    float mx = -3.402823466e38f;
    #pragma unroll
    for (int j = 0; j < 8; j++) {
        v[j] = row[t + j * 256];
        mx = fmaxf(mx, v[j]);
    }
    #pragma unroll
    for (int o = 16; o > 0; o >>= 1)
        mx = fmaxf(mx, __shfl_xor_sync(0xffffffffu, mx, o));
    if ((t & 31) == 0) sred[t >> 5] = mx;
    __syncthreads();
    mx = sred[0];
    #pragma unroll
    for (int w = 1; w < 8; w++) mx = fmaxf(mx, sred[w]);

    float s = 0.f;
    #pragma unroll
    for (int j = 0; j < 8; j++) {
        v[j] = expf(v[j] - mx);
        s += v[j];
    }
    #pragma unroll
    for (int o = 16; o > 0; o >>= 1)
        s += __shfl_xor_sync(0xffffffffu, s, o);
    __syncthreads();
    if ((t & 31) == 0) sred[t >> 5] = s;
    __syncthreads();
    s = 0.f;
    #pragma unroll
    for (int w = 0; w < 8; w++) s += sred[w];

    float inv = 1.f / s;
    #pragma unroll
    for (int j = 0; j < 8; j++)
        row[t + j * 256] = v[j] * inv;
}

// ---------------------------------------------------------------------------
extern "C" void kernel_launch(void* const* d_in, const int* in_sizes, int n_in,
                              void* d_out, int out_size)
{
    (void)in_sizes; (void)n_in; (void)out_size;
    const float* q     = (const float*)d_in[0];   // [QL, B, DIM]
    const float* c     = (const float*)d_in[1];   // [CL, B, DIM]
    const float* W_in  = (const float*)d_in[2];   // [DIM, DIM]
    const float* W_out = (const float*)d_in[3];   // [DIM, 2*DIM]

    float* out   = (float*)d_out;                         // [QL, B, DIM]
    float* score = out + (size_t)QL * BATCH * DIM;        // [B, QL, CL]

    float* qb  = nullptr;
    float* ctx = nullptr;
    cudaGetSymbolAddress((void**)&qb,  g_qb);
    cudaGetSymbolAddress((void**)&ctx, g_ctx);

    const long sQB  = (long)QL * DIM;      // 1M  per batch
    const long sSC  = (long)QL * CL;       // 2M  per batch

    // Stage 1: qb[b,q,e] = sum_d q[q,b,d] * W_in[e,d]
    {
        dim3 grid(DIM / BN, QL / BM, BATCH);
        gemm_tt_kernel<false, false><<<grid, 256>>>(
            q, nullptr, /*lda*/ (long)BATCH * DIM, /*sAb*/ DIM,
            W_in, /*ldb*/ DIM, /*sBb*/ 0,
            qb, /*ldc*/ DIM, /*sCb*/ sQB,
            DIM, 0);
    }

    // Stage 2: raw score[b,q,k] = sum_d qb[b,q,d] * c[k,b,d]  -> score region
    {
        dim3 grid(CL / BN, QL / BM, BATCH);
        gemm_tt_kernel<false, false><<<grid, 256>>>(
            qb, nullptr, /*lda*/ DIM, /*sAb*/ sQB,
            c, /*ldb*/ (long)BATCH * DIM, /*sBb*/ DIM,
            score, /*ldc*/ CL, /*sCb*/ sSC,
            DIM, 0);
    }

    // Stage 3: softmax in place over last dim (CL=2048)
    softmax2048_kernel<<<BATCH * QL, 256>>>(score);

    // Stage 4: ctx[b,q,d] = sum_k score[b,q,k] * c[k,b,d]
    {
        dim3 grid(DIM / BN, QL / BM, BATCH);
        gemm_tn_kernel<<<grid, 256>>>(
            score, /*lda*/ CL, /*sAb*/ sSC,
            c, /*ldb*/ (long)BATCH * DIM, /*sBb*/ DIM,
            ctx, /*ldc*/ DIM, /*sCb*/ sQB,
            CL);
    }

    // Stage 5: out[q,b,d] = tanh( sum_f [ctx|qb][b,q,f] * W_out[d,f] )
    {
        dim3 grid(DIM / BN, QL / BM, BATCH);
        gemm_tt_kernel<true, true><<<grid, 256>>>(
            ctx, qb, /*lda*/ DIM, /*sAb*/ sQB,
            W_out, /*ldb*/ 2 * DIM, /*sBb*/ 0,
            out + /*batch base via sCb*/ 0, /*ldc*/ (long)BATCH * DIM, /*sCb*/ DIM,
            2 * DIM, DIM);
    }
}

// round 4
// speedup vs baseline: 1.0001x; 1.0001x over previous
#include <cuda_runtime.h>
#include <math.h>

// Shapes (fixed for this problem)
#define QL 1024
#define CL 2048
#define BATCH 16
#define DIM 1024

#define BM 128
#define BN 128
#define BK 8
#define PAD 132   // padded smem row (in floats): conflict-free + 16B-aligned rows

// Scratch: qb and ctx, [b, q, dim] each = 64 MB
__device__ float g_qb [(size_t)BATCH * QL * DIM];
__device__ float g_ctx[(size_t)BATCH * QL * DIM];

// ---------------------------------------------------------------------------
// C = A * B^T  (A: M x K, K-contiguous with row stride lda;
//               B: N x K, K-contiguous with row stride ldb)
// Optional: CONCAT (A is [A0 | A1] along K, split at Ksplit), TANH epilogue.
// Tiles: 128x128x8, 256 threads, 8x8 per-thread register tile.
// ---------------------------------------------------------------------------
template<bool TANH, bool CONCAT>
__global__ __launch_bounds__(256, 2)
void gemm_tt_kernel(const float* __restrict__ A0, const float* __restrict__ A1,
                    long lda, long sAb,
                    const float* __restrict__ B, long ldb, long sBb,
                    float* __restrict__ C, long ldc, long sCb,
                    int K, int Ksplit)
{
    __shared__ float As[BK][PAD];
    __shared__ float Bs[BK][PAD];

    const int bi = blockIdx.z;
    const float* Ab0 = A0 + (long)bi * sAb;
    const float* Ab1 = CONCAT ? (A1 + (long)bi * sAb) : Ab0;
    const float* Bb  = B  + (long)bi * sBb;
    float*       Cb  = C  + (long)bi * sCb;

    const int m0 = blockIdx.y * BM;
    const int n0 = blockIdx.x * BN;
    const int tid  = threadIdx.x;
    const int lrow = tid >> 1;          // 0..127: tile row for global loads
    const int lk   = (tid & 1) * 4;     // 0 or 4: k offset for global loads
    const int tx   = tid & 15;
    const int ty   = tid >> 4;

    float acc[8][8];
    #pragma unroll
    for (int i = 0; i < 8; i++)
        #pragma unroll
        for (int j = 0; j < 8; j++) acc[i][j] = 0.f;

    for (int k0 = 0; k0 < K; k0 += BK) {
        const float* Aptr;
        int ka;
        if (CONCAT && k0 >= Ksplit) { Aptr = Ab1; ka = k0 - Ksplit; }
        else                        { Aptr = Ab0; ka = k0; }

        float4 av = *(const float4*)(Aptr + (long)(m0 + lrow) * lda + ka + lk);
        float4 bv = *(const float4*)(Bb   + (long)(n0 + lrow) * ldb + k0 + lk);

        __syncthreads();
        As[lk + 0][lrow] = av.x; As[lk + 1][lrow] = av.y;
        As[lk + 2][lrow] = av.z; As[lk + 3][lrow] = av.w;
        Bs[lk + 0][lrow] = bv.x; Bs[lk + 1][lrow] = bv.y;
        Bs[lk + 2][lrow] = bv.z; Bs[lk + 3][lrow] = bv.w;
        __syncthreads();

        #pragma unroll
        for (int kk = 0; kk < BK; kk++) {
            float a[8], b8[8];
            *(float4*)(a)     = *(const float4*)&As[kk][ty * 8];
            *(float4*)(a + 4) = *(const float4*)&As[kk][ty * 8 + 4];
            *(float4*)(b8)     = *(const float4*)&Bs[kk][tx * 8];
            *(float4*)(b8 + 4) = *(const float4*)&Bs[kk][tx * 8 + 4];
            #pragma unroll
            for (int i = 0; i < 8; i++)
                #pragma unroll
                for (int j = 0; j < 8; j++)
                    acc[i][j] += a[i] * b8[j];
        }
    }

    #pragma unroll
    for (int i = 0; i < 8; i++) {
        long rbase = (long)(m0 + ty * 8 + i) * ldc + n0 + tx * 8;
        #pragma unroll
        for (int j = 0; j < 8; j += 4) {
            float4 o;
            o.x = TANH ? tanhf(acc[i][j + 0]) : acc[i][j + 0];
            o.y = TANH ? tanhf(acc[i][j + 1]) : acc[i][j + 1];
            o.z = TANH ? tanhf(acc[i][j + 2]) : acc[i][j + 2];
            o.w = TANH ? tanhf(acc[i][j + 3]) : acc[i][j + 3];
            *(float4*)(Cb + rbase + j) = o;
        }
    }
}

// ---------------------------------------------------------------------------
// C = A * B  (A: M x K, K-contiguous, row stride lda;
//             B: K x N, N-contiguous, row stride ldb)
// ---------------------------------------------------------------------------
__global__ __launch_bounds__(256, 2)
void gemm_tn_kernel(const float* __restrict__ A, long lda, long sAb,
                    const float* __restrict__ B, long ldb, long sBb,
                    float* __restrict__ C, long ldc, long sCb, int K)
{
    __shared__ float As[BK][PAD];
    __shared__ float Bs[BK][PAD];

    const int bi = blockIdx.z;
    const float* Ab = A + (long)bi * sAb;
    const float* Bb = B + (long)bi * sBb;
    float*       Cb = C + (long)bi * sCb;

    const int m0 = blockIdx.y * BM;
    const int n0 = blockIdx.x * BN;
    const int tid  = threadIdx.x;
    const int lrow = tid >> 1;
    const int lk   = (tid & 1) * 4;
    const int brow = tid >> 5;          // 0..7: B tile k-row
    const int bcol = (tid & 31) * 4;    // 0..124
    const int tx   = tid & 15;
    const int ty   = tid >> 4;

    float acc[8][8];
    #pragma unroll
    for (int i = 0; i < 8; i++)
        #pragma unroll
        for (int j = 0; j < 8; j++) acc[i][j] = 0.f;

    for (int k0 = 0; k0 < K; k0 += BK) {
        float4 av = *(const float4*)(Ab + (long)(m0 + lrow) * lda + k0 + lk);
        float4 bv = *(const float4*)(Bb + (long)(k0 + brow) * ldb + n0 + bcol);

        __syncthreads();
        As[lk + 0][lrow] = av.x; As[lk + 1][lrow] = av.y;
        As[lk + 2][lrow] = av.z; As[lk + 3][lrow] = av.w;
        *(float4*)&Bs[brow][bcol] = bv;
        __syncthreads();

        #pragma unroll
        for (int kk = 0; kk < BK; kk++) {
            float a[8], b8[8];
            *(float4*)(a)     = *(const float4*)&As[kk][ty * 8];
            *(float4*)(a + 4) = *(const float4*)&As[kk][ty * 8 + 4];
            *(float4*)(b8)     = *(const float4*)&Bs[kk][tx * 8];
            *(float4*)(b8 + 4) = *(const float4*)&Bs[kk][tx * 8 + 4];
            #pragma unroll
            for (int i = 0; i < 8; i++)
                #pragma unroll
                for (int j = 0; j < 8; j++)
                    acc[i][j] += a[i] * b8[j];
        }
    }

    #pragma unroll
    for (int i = 0; i < 8; i++) {
        long rbase = (long)(m0 + ty * 8 + i) * ldc + n0 + tx * 8;
        #pragma unroll
        for (int j = 0; j < 8; j += 4) {
            float4 o;
            o.x = acc[i][j + 0]; o.y = acc[i][j + 1];
            o.z = acc[i][j + 2]; o.w = acc[i][j + 3];
            *(float4*)(Cb + rbase + j) = o;
        }
    }
}

// ---------------------------------------------------------------------------
// In-place softmax over rows of 2048 (one block per row, 256 threads x 8 elems)
// ---------------------------------------------------------------------------
__global__ __launch_bounds__(256)
void softmax2048_kernel(float* __restrict__ S)
{
    float* row = S + (long)blockIdx.x * 2048;
    const int t = threadIdx.x;
    __shared__ float sred[8];

    float v[8];
    float mx = -3.402823466e38f;
    #pragma unroll
    for (int j = 0; j < 8; j++) {
        v[j] = row[t + j * 256];
        mx = fmaxf(mx, v[j]);
    }
    #pragma unroll
    for (int o = 16; o > 0; o >>= 1)
        mx = fmaxf(mx, __shfl_xor_sync(0xffffffffu, mx, o));
    if ((t & 31) == 0) sred[t >> 5] = mx;
    __syncthreads();
    mx = sred[0];
    #pragma unroll
    for (int w = 1; w < 8; w++) mx = fmaxf(mx, sred[w]);

    float s = 0.f;
    #pragma unroll
    for (int j = 0; j < 8; j++) {
        v[j] = expf(v[j] - mx);
        s += v[j];
    }
    #pragma unroll
    for (int o = 16; o > 0; o >>= 1)
        s += __shfl_xor_sync(0xffffffffu, s, o);
    __syncthreads();
    if ((t & 31) == 0) sred[t >> 5] = s;
    __syncthreads();
    s = 0.f;
    #pragma unroll
    for (int w = 0; w < 8; w++) s += sred[w];

    float inv = 1.f / s;
    #pragma unroll
    for (int j = 0; j < 8; j++)
        row[t + j * 256] = v[j] * inv;
}

// ---------------------------------------------------------------------------
extern "C" void kernel_launch(void* const* d_in, const int* in_sizes, int n_in,
                              void* d_out, int out_size)
{
    (void)in_sizes; (void)n_in; (void)out_size;
    const float* q     = (const float*)d_in[0];   // [QL, B, DIM]
    const float* c     = (const float*)d_in[1];   // [CL, B, DIM]
    const float* W_in  = (const float*)d_in[2];   // [DIM, DIM]
    const float* W_out = (const float*)d_in[3];   // [DIM, 2*DIM]

    float* out   = (float*)d_out;                         // [QL, B, DIM]
    float* score = out + (size_t)QL * BATCH * DIM;        // [B, QL, CL]

    float* qb  = nullptr;
    float* ctx = nullptr;
    cudaGetSymbolAddress((void**)&qb,  g_qb);
    cudaGetSymbolAddress((void**)&ctx, g_ctx);

    const long sQB  = (long)QL * DIM;      // 1M  per batch
    const long sSC  = (long)QL * CL;       // 2M  per batch

    // Stage 1: qb[b,q,e] = sum_d q[q,b,d] * W_in[e,d]
    {
        dim3 grid(DIM / BN, QL / BM, BATCH);
        gemm_tt_kernel<false, false><<<grid, 256>>>(
            q, nullptr, /*lda*/ (long)BATCH * DIM, /*sAb*/ DIM,
            W_in, /*ldb*/ DIM, /*sBb*/ 0,
            qb, /*ldc*/ DIM, /*sCb*/ sQB,
            DIM, 0);
    }

    // Stage 2: raw score[b,q,k] = sum_d qb[b,q,d] * c[k,b,d]  -> score region
    {
        dim3 grid(CL / BN, QL / BM, BATCH);
        gemm_tt_kernel<false, false><<<grid, 256>>>(
            qb, nullptr, /*lda*/ DIM, /*sAb*/ sQB,
            c, /*ldb*/ (long)BATCH * DIM, /*sBb*/ DIM,
            score, /*ldc*/ CL, /*sCb*/ sSC,
            DIM, 0);
    }

    // Stage 3: softmax in place over last dim (CL=2048)
    softmax2048_kernel<<<BATCH * QL, 256>>>(score);

    // Stage 4: ctx[b,q,d] = sum_k score[b,q,k] * c[k,b,d]
    {
        dim3 grid(DIM / BN, QL / BM, BATCH);
        gemm_tn_kernel<<<grid, 256>>>(
            score, /*lda*/ CL, /*sAb*/ sSC,
            c, /*ldb*/ (long)BATCH * DIM, /*sBb*/ DIM,
            ctx, /*ldc*/ DIM, /*sCb*/ sQB,
            CL);
    }

    // Stage 5: out[q,b,d] = tanh( sum_f [ctx|qb][b,q,f] * W_out[d,f] )
    {
        dim3 grid(DIM / BN, QL / BM, BATCH);
        gemm_tt_kernel<true, true><<<grid, 256>>>(
            ctx, qb, /*lda*/ DIM, /*sAb*/ sQB,
            W_out, /*ldb*/ 2 * DIM, /*sBb*/ 0,
            out + /*batch base via sCb*/ 0, /*ldc*/ (long)BATCH * DIM, /*sCb*/ DIM,
            2 * DIM, DIM);
    }
}

// round 5
// speedup vs baseline: 1.0002x; 1.0001x over previous
#include <cuda_runtime.h>
#include <math.h>

// Shapes (fixed for this problem)
#define QL 1024
#define CL 2048
#define BATCH 16
#define DIM 1024

#define BM 128
#define BN 128
#define BK 8
#define PAD 132   // padded smem row (in floats): conflict-free + 16B-aligned rows

// Scratch: qb and ctx, [b, q, dim] each = 64 MB
__device__ float g_qb [(size_t)BATCH * QL * DIM];
__device__ float g_ctx[(size_t)BATCH * QL * DIM];

// ---------------------------------------------------------------------------
// C = A * B^T  (A: M x K, K-contiguous with row stride lda;
//               B: N x K, K-contiguous with row stride ldb)
// Optional: CONCAT (A is [A0 | A1] along K, split at Ksplit), TANH epilogue.
// Tiles: 128x128x8, 256 threads, 8x8 per-thread register tile.
// ---------------------------------------------------------------------------
template<bool TANH, bool CONCAT>
__global__ __launch_bounds__(256, 2)
void gemm_tt_kernel(const float* __restrict__ A0, const float* __restrict__ A1,
                    long lda, long sAb,
                    const float* __restrict__ B, long ldb, long sBb,
                    float* __restrict__ C, long ldc, long sCb,
                    int K, int Ksplit)
{
    __shared__ float As[BK][PAD];
    __shared__ float Bs[BK][PAD];

    const int bi = blockIdx.z;
    const float* Ab0 = A0 + (long)bi * sAb;
    const float* Ab1 = CONCAT ? (A1 + (long)bi * sAb) : Ab0;
    const float* Bb  = B  + (long)bi * sBb;
    float*       Cb  = C  + (long)bi * sCb;

    const int m0 = blockIdx.y * BM;
    const int n0 = blockIdx.x * BN;
    const int tid  = threadIdx.x;
    const int lrow = tid >> 1;          // 0..127: tile row for global loads
    const int lk   = (tid & 1) * 4;     // 0 or 4: k offset for global loads
    const int tx   = tid & 15;
    const int ty   = tid >> 4;

    float acc[8][8];
    #pragma unroll
    for (int i = 0; i < 8; i++)
        #pragma unroll
        for (int j = 0; j < 8; j++) acc[i][j] = 0.f;

    for (int k0 = 0; k0 < K; k0 += BK) {
        const float* Aptr;
        int ka;
        if (CONCAT && k0 >= Ksplit) { Aptr = Ab1; ka = k0 - Ksplit; }
        else                        { Aptr = Ab0; ka = k0; }

        float4 av = *(const float4*)(Aptr + (long)(m0 + lrow) * lda + ka + lk);
        float4 bv = *(const float4*)(Bb   + (long)(n0 + lrow) * ldb + k0 + lk);

        __syncthreads();
        As[lk + 0][lrow] = av.x; As[lk + 1][lrow] = av.y;
        As[lk + 2][lrow] = av.z; As[lk + 3][lrow] = av.w;
        Bs[lk + 0][lrow] = bv.x; Bs[lk + 1][lrow] = bv.y;
        Bs[lk + 2][lrow] = bv.z; Bs[lk + 3][lrow] = bv.w;
        __syncthreads();

        #pragma unroll
        for (int kk = 0; kk < BK; kk++) {
            float a[8], b8[8];
            *(float4*)(a)     = *(const float4*)&As[kk][ty * 8];
            *(float4*)(a + 4) = *(const float4*)&As[kk][ty * 8 + 4];
            *(float4*)(b8)     = *(const float4*)&Bs[kk][tx * 8];
            *(float4*)(b8 + 4) = *(const float4*)&Bs[kk][tx * 8 + 4];
            #pragma unroll
            for (int i = 0; i < 8; i++)
                #pragma unroll
                for (int j = 0; j < 8; j++)
                    acc[i][j] += a[i] * b8[j];
        }
    }

    #pragma unroll
    for (int i = 0; i < 8; i++) {
        long rbase = (long)(m0 + ty * 8 + i) * ldc + n0 + tx * 8;
        #pragma unroll
        for (int j = 0; j < 8; j += 4) {
            float4 o;
            o.x = TANH ? tanhf(acc[i][j + 0]) : acc[i][j + 0];
            o.y = TANH ? tanhf(acc[i][j + 1]) : acc[i][j + 1];
            o.z = TANH ? tanhf(acc[i][j + 2]) : acc[i][j + 2];
            o.w = TANH ? tanhf(acc[i][j + 3]) : acc[i][j + 3];
            *(float4*)(Cb + rbase + j) = o;
        }
    }
}

// ---------------------------------------------------------------------------
// C = A * B  (A: M x K, K-contiguous, row stride lda;
//             B: K x N, N-contiguous, row stride ldb)
// ---------------------------------------------------------------------------
__global__ __launch_bounds__(256, 2)
void gemm_tn_kernel(const float* __restrict__ A, long lda, long sAb,
                    const float* __restrict__ B, long ldb, long sBb,
                    float* __restrict__ C, long ldc, long sCb, int K)
{
    __shared__ float As[BK][PAD];
    __shared__ float Bs[BK][PAD];

    const int bi = blockIdx.z;
    const float* Ab = A + (long)bi * sAb;
    const float* Bb = B + (long)bi * sBb;
    float*       Cb = C + (long)bi * sCb;

    const int m0 = blockIdx.y * BM;
    const int n0 = blockIdx.x * BN;
    const int tid  = threadIdx.x;
    const int lrow = tid >> 1;
    const int lk   = (tid & 1) * 4;
    const int brow = tid >> 5;          // 0..7: B tile k-row
    const int bcol = (tid & 31) * 4;    // 0..124
    const int tx   = tid & 15;
    const int ty   = tid >> 4;

    float acc[8][8];
    #pragma unroll
    for (int i = 0; i < 8; i++)
        #pragma unroll
        for (int j = 0; j < 8; j++) acc[i][j] = 0.f;

    for (int k0 = 0; k0 < K; k0 += BK) {
        float4 av = *(const float4*)(Ab + (long)(m0 + lrow) * lda + k0 + lk);
        float4 bv = *(const float4*)(Bb + (long)(k0 + brow) * ldb + n0 + bcol);

        __syncthreads();
        As[lk + 0][lrow] = av.x; As[lk + 1][lrow] = av.y;
        As[lk + 2][lrow] = av.z; As[lk + 3][lrow] = av.w;
        *(float4*)&Bs[brow][bcol] = bv;
        __syncthreads();

        #pragma unroll
        for (int kk = 0; kk < BK; kk++) {
            float a[8], b8[8];
            *(float4*)(a)     = *(const float4*)&As[kk][ty * 8];
            *(float4*)(a + 4) = *(const float4*)&As[kk][ty * 8 + 4];
            *(float4*)(b8)     = *(const float4*)&Bs[kk][tx * 8];
            *(float4*)(b8 + 4) = *(const float4*)&Bs[kk][tx * 8 + 4];
            #pragma unroll
            for (int i = 0; i < 8; i++)
                #pragma unroll
                for (int j = 0; j < 8; j++)
                    acc[i][j] += a[i] * b8[j];
        }
    }

    #pragma unroll
    for (int i = 0; i < 8; i++) {
        long rbase = (long)(m0 + ty * 8 + i) * ldc + n0 + tx * 8;
        #pragma unroll
        for (int j = 0; j < 8; j += 4) {
            float4 o;
            o.x = acc[i][j + 0]; o.y = acc[i][j + 1];
            o.z = acc[i][j + 2]; o.w = acc[i][j + 3];
            *(float4*)(Cb + rbase + j) = o;
        }
    }
}

// ---------------------------------------------------------------------------
// In-place softmax over rows of 2048 (one block per row, 256 threads x 8 elems)
// ---------------------------------------------------------------------------
__global__ __launch_bounds__(256)
void softmax2048_kernel(float* __restrict__ S)
{
    float* row = S + (long)blockIdx.x * 2048;
    const int t = threadIdx.x;
    __shared__ float sred[8];

    float v[8];
    float mx = -3.402823466e38f;
    #pragma unroll
    for (int j = 0; j < 8; j++) {
        v[j] = row[t + j * 256];
        mx = fmaxf(mx, v[j]);
    }
    #pragma unroll
    for (int o = 16; o > 0; o >>= 1)
        mx = fmaxf(mx, __shfl_xor_sync(0xffffffffu, mx, o));
    if ((t & 31) == 0) sred[t >> 5] = mx;
    __syncthreads();
    mx = sred[0];
    #pragma unroll
    for (int w = 1; w < 8; w++) mx = fmaxf(mx, sred[w]);

    float s = 0.f;
    #pragma unroll
    for (int j = 0; j < 8; j++) {
        v[j] = expf(v[j] - mx);
        s += v[j];
    }
    #pragma unroll
    for (int o = 16; o > 0; o >>= 1)
        s += __shfl_xor_sync(0xffffffffu, s, o);
    __syncthreads();
    if ((t & 31) == 0) sred[t >> 5] = s;
    __syncthreads();
    s = 0.f;
    #pragma unroll
    for (int w = 0; w < 8; w++) s += sred[w];

    float inv = 1.f / s;
    #pragma unroll
    for (int j = 0; j < 8; j++)
        row[t + j * 256] = v[j] * inv;
}

// ---------------------------------------------------------------------------
extern "C" void kernel_launch(void* const* d_in, const int* in_sizes, int n_in,
                              void* d_out, int out_size)
{
    (void)in_sizes; (void)n_in; (void)out_size;
    const float* q     = (const float*)d_in[0];   // [QL, B, DIM]
    const float* c     = (const float*)d_in[1];   // [CL, B, DIM]
    const float* W_in  = (const float*)d_in[2];   // [DIM, DIM]
    const float* W_out = (const float*)d_in[3];   // [DIM, 2*DIM]

    float* out   = (float*)d_out;                         // [QL, B, DIM]
    float* score = out + (size_t)QL * BATCH * DIM;        // [B, QL, CL]

    float* qb  = nullptr;
    float* ctx = nullptr;
    cudaGetSymbolAddress((void**)&qb,  g_qb);
    cudaGetSymbolAddress((void**)&ctx, g_ctx);

    const long sQB  = (long)QL * DIM;      // 1M  per batch
    const long sSC  = (long)QL * CL;       // 2M  per batch

    // Stage 1: qb[b,q,e] = sum_d q[q,b,d] * W_in[e,d]
    {
        dim3 grid(DIM / BN, QL / BM, BATCH);
        gemm_tt_kernel<false, false><<<grid, 256>>>(
            q, nullptr, /*lda*/ (long)BATCH * DIM, /*sAb*/ DIM,
            W_in, /*ldb*/ DIM, /*sBb*/ 0,
            qb, /*ldc*/ DIM, /*sCb*/ sQB,
            DIM, 0);
    }

    // Stage 2: raw score[b,q,k] = sum_d qb[b,q,d] * c[k,b,d]  -> score region
    {
        dim3 grid(CL / BN, QL / BM, BATCH);
        gemm_tt_kernel<false, false><<<grid, 256>>>(
            qb, nullptr, /*lda*/ DIM, /*sAb*/ sQB,
            c, /*ldb*/ (long)BATCH * DIM, /*sBb*/ DIM,
            score, /*ldc*/ CL, /*sCb*/ sSC,
            DIM, 0);
    }

    // Stage 3: softmax in place over last dim (CL=2048)
    softmax2048_kernel<<<BATCH * QL, 256>>>(score);

    // Stage 4: ctx[b,q,d] = sum_k score[b,q,k] * c[k,b,d]
    {
        dim3 grid(DIM / BN, QL / BM, BATCH);
        gemm_tn_kernel<<<grid, 256>>>(
            score, /*lda*/ CL, /*sAb*/ sSC,
            c, /*ldb*/ (long)BATCH * DIM, /*sBb*/ DIM,
            ctx, /*ldc*/ DIM, /*sCb*/ sQB,
            CL);
    }

    // Stage 5: out[q,b,d] = tanh( sum_f [ctx|qb][b,q,f] * W_out[d,f] )
    {
        dim3 grid(DIM / BN, QL / BM, BATCH);
        gemm_tt_kernel<true, true><<<grid, 256>>>(
            ctx, qb, /*lda*/ DIM, /*sAb*/ sQB,
            W_out, /*ldb*/ 2 * DIM, /*sBb*/ 0,
            out + /*batch base via sCb*/ 0, /*ldc*/ (long)BATCH * DIM, /*sCb*/ DIM,
            2 * DIM, DIM);
    }
}

// round 6
// speedup vs baseline: 1.5105x; 1.5102x over previous
#include <cuda_runtime.h>
#include <cstdint>
#include <math.h>

// Shapes (fixed)
#define QL 1024
#define CL 2048
#define BATCH 16
#define DIM 1024

// GEMM tiling
#define BM 128
#define BN 64
#define BK 16
#define SA  20   // A smem row stride (floats): 128x16 tile, conflict-free fragment LDS
#define SBT 20   // B smem row stride, k-contiguous (BT) layout
#define SBN 72   // B smem row stride, n-contiguous (BN) layout (16 rows x 64+8)

// Scratch: qb and ctx, [b, q, dim] each = 64 MB
__device__ float g_qb [(size_t)BATCH * QL * DIM];
__device__ float g_ctx[(size_t)BATCH * QL * DIM];

// ---------------------------------------------------------------------------
// helpers
// ---------------------------------------------------------------------------
__device__ __forceinline__ void cp16(uint32_t dst, const float* src) {
    asm volatile("cp.async.cg.shared.global [%0], [%1], 16;" :: "r"(dst), "l"(src));
}
__device__ __forceinline__ void cp_commit() { asm volatile("cp.async.commit_group;" ::: "memory"); }
__device__ __forceinline__ void cp_wait1()  { asm volatile("cp.async.wait_group 1;"  ::: "memory"); }

// 2-way tf32 split: hi = top-10-mantissa truncation, lo = exact residual.
// Dropped Al*Bl term is O(eps^2) ~ 1e-6 relative -> ~1e-5 overall rel_err.
__device__ __forceinline__ void split2(float f, uint32_t& hi, uint32_t& lo) {
    uint32_t u = __float_as_uint(f) & 0xFFFFE000u;
    hi = u;
    lo = __float_as_uint(f - __uint_as_float(u));
}

__device__ __forceinline__ void mma8(float* d, const uint32_t* a, const uint32_t* b) {
    asm volatile(
        "mma.sync.aligned.m16n8k8.row.col.f32.tf32.tf32.f32 "
        "{%0,%1,%2,%3}, {%4,%5,%6,%7}, {%8,%9}, {%0,%1,%2,%3};"
        : "+f"(d[0]), "+f"(d[1]), "+f"(d[2]), "+f"(d[3])
        : "r"(a[0]), "r"(a[1]), "r"(a[2]), "r"(a[3]), "r"(b[0]), "r"(b[1]));
}

// ---------------------------------------------------------------------------
// C[m][n] = sum_k A[m][k] * B'[k][n], fp32 in/out, 3xTF32 tensor-core compute.
//   A: row-major, K-contiguous rows, stride lda. CONCAT: [A0|A1] split at Ksplit.
//   B: BKC=true : N rows of K-contiguous data, stride ldb (i.e. B'[k][n]=B[n][k])
//      BKC=false: K rows of N-contiguous data, stride ldb (i.e. B'[k][n]=B[k][n])
// Tiles 128x64x16, 256 threads (warps 4m x 2n; warp tile 32x32),
// double-buffered cp.async pipeline.
// ---------------------------------------------------------------------------
template<bool TANH, bool CONCAT, bool BKC>
__global__ __launch_bounds__(256, 2)
void gemm3t_kernel(const float* __restrict__ A0, const float* __restrict__ A1,
                   long lda, long sAb,
                   const float* __restrict__ B, long ldb, long sBb,
                   float* __restrict__ C, long ldc, long sCb,
                   int K, int Ksplit)
{
    __shared__ float As[2][BM * SA];     // 2 x 2560 floats
    __shared__ float Bs[2][1280];        // max(BN*SBT=1280, BK*SBN=1152)

    const int bi = blockIdx.z;
    const float* Ab0 = A0 + (long)bi * sAb;
    const float* Ab1 = CONCAT ? (A1 + (long)bi * sAb) : Ab0;
    const float* Bb  = B + (long)bi * sBb;
    float*       Cb  = C + (long)bi * sCb;

    const int m0 = blockIdx.y * BM;
    const int n0 = blockIdx.x * BN;
    const int tid  = threadIdx.x;
    const int lane = tid & 31;
    const int wid  = tid >> 5;
    const int wm = (wid & 3) * 32;     // warp m offset within block tile
    const int wn = (wid >> 2) * 32;    // warp n offset
    const int g  = lane >> 2;          // groupID (0..7)
    const int t  = lane & 3;           // threadID_in_group (0..3)

    // global->smem load assignments
    const int ar  = tid >> 2;          // 0..63 (A rows; also +64)
    const int akq = (tid & 3) * 4;     // k quad
    const int bkr = tid >> 4;          // 0..15 (BN layout k row)
    const int bnq = (tid & 15) * 4;    // n quad

    const uint32_t sA_base = (uint32_t)__cvta_generic_to_shared(&As[0][0]);
    const uint32_t sB_base = (uint32_t)__cvta_generic_to_shared(&Bs[0][0]);

    float acc[2][4][4];
    #pragma unroll
    for (int i = 0; i < 2; i++)
        #pragma unroll
        for (int j = 0; j < 4; j++)
            #pragma unroll
            for (int r = 0; r < 4; r++) acc[i][j][r] = 0.f;

    const int niter = K / BK;

    auto prefetch = [&](int it, int buf) {
        const int k0 = it * BK;
        const float* Ap; int ka;
        if (CONCAT && k0 >= Ksplit) { Ap = Ab1; ka = k0 - Ksplit; }
        else                        { Ap = Ab0; ka = k0; }
        const uint32_t sa = sA_base + (uint32_t)buf * (BM * SA * 4);
        const float* s0 = Ap + (long)(m0 + ar) * lda + ka + akq;
        cp16(sa + (uint32_t)(ar * SA + akq) * 4, s0);
        cp16(sa + (uint32_t)((ar + 64) * SA + akq) * 4, s0 + 64 * lda);
        const uint32_t sb = sB_base + (uint32_t)buf * (1280 * 4);
        if (BKC) {
            cp16(sb + (uint32_t)(ar * SBT + akq) * 4,
                 Bb + (long)(n0 + ar) * ldb + k0 + akq);
        } else {
            cp16(sb + (uint32_t)(bkr * SBN + bnq) * 4,
                 Bb + (long)(k0 + bkr) * ldb + n0 + bnq);
        }
    };

    prefetch(0, 0);
    cp_commit();

    for (int it = 0; it < niter; it++) {
        const int buf = it & 1;
        if (it + 1 < niter) prefetch(it + 1, buf ^ 1);
        cp_commit();
        cp_wait1();
        __syncthreads();

        const float* as = &As[buf][0];
        const float* bs = &Bs[buf][0];

        #pragma unroll
        for (int kc = 0; kc < BK; kc += 8) {
            // A fragments (m16n8k8.row layout), split into hi/lo tf32
            uint32_t ah[2][4], al[2][4];
            #pragma unroll
            for (int i = 0; i < 2; i++) {
                const int r0 = wm + i * 16 + g;
                split2(as[r0 * SA + kc + t],           ah[i][0], al[i][0]);
                split2(as[(r0 + 8) * SA + kc + t],     ah[i][1], al[i][1]);
                split2(as[r0 * SA + kc + t + 4],       ah[i][2], al[i][2]);
                split2(as[(r0 + 8) * SA + kc + t + 4], ah[i][3], al[i][3]);
            }
            // B fragments
            uint32_t bh[4][2], bl[4][2];
            #pragma unroll
            for (int j = 0; j < 4; j++) {
                float f0, f1;
                if (BKC) {
                    const int n = wn + j * 8 + g;
                    f0 = bs[n * SBT + kc + t];
                    f1 = bs[n * SBT + kc + t + 4];
                } else {
                    const int n = wn + j * 8 + g;
                    f0 = bs[(kc + t) * SBN + n];
                    f1 = bs[(kc + t + 4) * SBN + n];
                }
                split2(f0, bh[j][0], bl[j][0]);
                split2(f1, bh[j][1], bl[j][1]);
            }
            // 3xTF32: D += Ah*Bh + Al*Bh + Ah*Bl
            #pragma unroll
            for (int i = 0; i < 2; i++)
                #pragma unroll
                for (int j = 0; j < 4; j++) {
                    mma8(acc[i][j], ah[i], bh[j]);
                    mma8(acc[i][j], al[i], bh[j]);
                    mma8(acc[i][j], ah[i], bl[j]);
                }
        }
        __syncthreads();
    }

    // epilogue: c0(g,2t) c1(g,2t+1) c2(g+8,2t) c3(g+8,2t+1)
    #pragma unroll
    for (int i = 0; i < 2; i++) {
        const int r0 = m0 + wm + i * 16 + g;
        #pragma unroll
        for (int j = 0; j < 4; j++) {
            const int cc = n0 + wn + j * 8 + t * 2;
            float d0 = acc[i][j][0], d1 = acc[i][j][1];
            float d2 = acc[i][j][2], d3 = acc[i][j][3];
            if (TANH) { d0 = tanhf(d0); d1 = tanhf(d1); d2 = tanhf(d2); d3 = tanhf(d3); }
            *(float2*)&Cb[(long)r0 * ldc + cc]       = make_float2(d0, d1);
            *(float2*)&Cb[(long)(r0 + 8) * ldc + cc] = make_float2(d2, d3);
        }
    }
}

// ---------------------------------------------------------------------------
// In-place softmax over rows of 2048 (one block per row, 256 threads x 8)
// ---------------------------------------------------------------------------
__global__ __launch_bounds__(256)
void softmax2048_kernel(float* __restrict__ S)
{
    float* row = S + (long)blockIdx.x * 2048;
    const int t = threadIdx.x;
    __shared__ float sred[8];

    float v[8];
    float mx = -3.402823466e38f;
    #pragma unroll
    for (int j = 0; j < 8; j++) {
        v[j] = row[t + j * 256];
        mx = fmaxf(mx, v[j]);
    }
    #pragma unroll
    for (int o = 16; o > 0; o >>= 1)
        mx = fmaxf(mx, __shfl_xor_sync(0xffffffffu, mx, o));
    if ((t & 31) == 0) sred[t >> 5] = mx;
    __syncthreads();
    mx = sred[0];
    #pragma unroll
    for (int w = 1; w < 8; w++) mx = fmaxf(mx, sred[w]);

    float s = 0.f;
    #pragma unroll
    for (int j = 0; j < 8; j++) {
        v[j] = expf(v[j] - mx);
        s += v[j];
    }
    #pragma unroll
    for (int o = 16; o > 0; o >>= 1)
        s += __shfl_xor_sync(0xffffffffu, s, o);
    __syncthreads();
    if ((t & 31) == 0) sred[t >> 5] = s;
    __syncthreads();
    s = 0.f;
    #pragma unroll
    for (int w = 0; w < 8; w++) s += sred[w];

    float inv = 1.f / s;
    #pragma unroll
    for (int j = 0; j < 8; j++)
        row[t + j * 256] = v[j] * inv;
}

// ---------------------------------------------------------------------------
extern "C" void kernel_launch(void* const* d_in, const int* in_sizes, int n_in,
                              void* d_out, int out_size)
{
    (void)in_sizes; (void)n_in; (void)out_size;
    const float* q     = (const float*)d_in[0];   // [QL, B, DIM]
    const float* c     = (const float*)d_in[1];   // [CL, B, DIM]
    const float* W_in  = (const float*)d_in[2];   // [DIM, DIM]
    const float* W_out = (const float*)d_in[3];   // [DIM, 2*DIM]

    float* out   = (float*)d_out;                       // [QL, B, DIM]
    float* score = out + (size_t)QL * BATCH * DIM;      // [B, QL, CL]

    float* qb  = nullptr;
    float* ctx = nullptr;
    cudaGetSymbolAddress((void**)&qb,  g_qb);
    cudaGetSymbolAddress((void**)&ctx, g_ctx);

    const long sQB = (long)QL * DIM;
    const long sSC = (long)QL * CL;

    // Stage 1: qb[b,q,e] = sum_d q[q,b,d] * W_in[e,d]
    {
        dim3 grid(DIM / BN, QL / BM, BATCH);
        gemm3t_kernel<false, false, true><<<grid, 256>>>(
            q, nullptr, (long)BATCH * DIM, DIM,
            W_in, DIM, 0,
            qb, DIM, sQB,
            DIM, 0);
    }

    // Stage 2: raw score[b,q,k] = sum_d qb[b,q,d] * c[k,b,d]
    {
        dim3 grid(CL / BN, QL / BM, BATCH);
        gemm3t_kernel<false, false, true><<<grid, 256>>>(
            qb, nullptr, DIM, sQB,
            c, (long)BATCH * DIM, DIM,
            score, CL, sSC,
            DIM, 0);
    }

    // Stage 3: softmax in place over last dim (CL=2048)
    softmax2048_kernel<<<BATCH * QL, 256>>>(score);

    // Stage 4: ctx[b,q,d] = sum_k score[b,q,k] * c[k,b,d]   (B is n-contiguous)
    {
        dim3 grid(DIM / BN, QL / BM, BATCH);
        gemm3t_kernel<false, false, false><<<grid, 256>>>(
            score, nullptr, CL, sSC,
            c, (long)BATCH * DIM, DIM,
            ctx, DIM, sQB,
            CL, 0);
    }

    // Stage 5: out[q,b,d] = tanh( sum_f [ctx|qb][b,q,f] * W_out[d,f] )
    {
        dim3 grid(DIM / BN, QL / BM, BATCH);
        gemm3t_kernel<true, true, true><<<grid, 256>>>(
            ctx, qb, DIM, sQB,
            W_out, 2 * DIM, 0,
            out, (long)BATCH * DIM, DIM,
            2 * DIM, DIM);
    }
}

// round 7
// speedup vs baseline: 1.5113x; 1.0005x over previous
#include <cuda_runtime.h>
#include <cstdint>
#include <math.h>

// Shapes (fixed)
#define QL 1024
#define CL 2048
#define BATCH 16
#define DIM 1024

// GEMM tiling
#define BM 128
#define BN 64
#define BK 16
#define SA  20   // A smem row stride (floats): 128x16 tile, conflict-free fragment LDS
#define SBT 20   // B smem row stride, k-contiguous (BT) layout
#define SBN 72   // B smem row stride, n-contiguous (BN) layout (16 rows x 64+8)

// Scratch: qb and ctx, [b, q, dim] each = 64 MB
__device__ float g_qb [(size_t)BATCH * QL * DIM];
__device__ float g_ctx[(size_t)BATCH * QL * DIM];

// ---------------------------------------------------------------------------
// helpers
// ---------------------------------------------------------------------------
__device__ __forceinline__ void cp16(uint32_t dst, const float* src) {
    asm volatile("cp.async.cg.shared.global [%0], [%1], 16;" :: "r"(dst), "l"(src));
}
__device__ __forceinline__ void cp_commit() { asm volatile("cp.async.commit_group;" ::: "memory"); }
__device__ __forceinline__ void cp_wait1()  { asm volatile("cp.async.wait_group 1;"  ::: "memory"); }

// 2-way tf32 split: hi = top-10-mantissa truncation, lo = exact residual.
// Dropped Al*Bl term is O(eps^2) ~ 1e-6 relative -> ~1e-5 overall rel_err.
__device__ __forceinline__ void split2(float f, uint32_t& hi, uint32_t& lo) {
    uint32_t u = __float_as_uint(f) & 0xFFFFE000u;
    hi = u;
    lo = __float_as_uint(f - __uint_as_float(u));
}

__device__ __forceinline__ void mma8(float* d, const uint32_t* a, const uint32_t* b) {
    asm volatile(
        "mma.sync.aligned.m16n8k8.row.col.f32.tf32.tf32.f32 "
        "{%0,%1,%2,%3}, {%4,%5,%6,%7}, {%8,%9}, {%0,%1,%2,%3};"
        : "+f"(d[0]), "+f"(d[1]), "+f"(d[2]), "+f"(d[3])
        : "r"(a[0]), "r"(a[1]), "r"(a[2]), "r"(a[3]), "r"(b[0]), "r"(b[1]));
}

// ---------------------------------------------------------------------------
// C[m][n] = sum_k A[m][k] * B'[k][n], fp32 in/out, 3xTF32 tensor-core compute.
//   A: row-major, K-contiguous rows, stride lda. CONCAT: [A0|A1] split at Ksplit.
//   B: BKC=true : N rows of K-contiguous data, stride ldb (i.e. B'[k][n]=B[n][k])
//      BKC=false: K rows of N-contiguous data, stride ldb (i.e. B'[k][n]=B[k][n])
// Tiles 128x64x16, 256 threads (warps 4m x 2n; warp tile 32x32),
// double-buffered cp.async pipeline.
// ---------------------------------------------------------------------------
template<bool TANH, bool CONCAT, bool BKC>
__global__ __launch_bounds__(256, 2)
void gemm3t_kernel(const float* __restrict__ A0, const float* __restrict__ A1,
                   long lda, long sAb,
                   const float* __restrict__ B, long ldb, long sBb,
                   float* __restrict__ C, long ldc, long sCb,
                   int K, int Ksplit)
{
    __shared__ float As[2][BM * SA];     // 2 x 2560 floats
    __shared__ float Bs[2][1280];        // max(BN*SBT=1280, BK*SBN=1152)

    const int bi = blockIdx.z;
    const float* Ab0 = A0 + (long)bi * sAb;
    const float* Ab1 = CONCAT ? (A1 + (long)bi * sAb) : Ab0;
    const float* Bb  = B + (long)bi * sBb;
    float*       Cb  = C + (long)bi * sCb;

    const int m0 = blockIdx.y * BM;
    const int n0 = blockIdx.x * BN;
    const int tid  = threadIdx.x;
    const int lane = tid & 31;
    const int wid  = tid >> 5;
    const int wm = (wid & 3) * 32;     // warp m offset within block tile
    const int wn = (wid >> 2) * 32;    // warp n offset
    const int g  = lane >> 2;          // groupID (0..7)
    const int t  = lane & 3;           // threadID_in_group (0..3)

    // global->smem load assignments
    const int ar  = tid >> 2;          // 0..63 (A rows; also +64)
    const int akq = (tid & 3) * 4;     // k quad
    const int bkr = tid >> 4;          // 0..15 (BN layout k row)
    const int bnq = (tid & 15) * 4;    // n quad

    const uint32_t sA_base = (uint32_t)__cvta_generic_to_shared(&As[0][0]);
    const uint32_t sB_base = (uint32_t)__cvta_generic_to_shared(&Bs[0][0]);

    float acc[2][4][4];
    #pragma unroll
    for (int i = 0; i < 2; i++)
        #pragma unroll
        for (int j = 0; j < 4; j++)
            #pragma unroll
            for (int r = 0; r < 4; r++) acc[i][j][r] = 0.f;

    const int niter = K / BK;

    auto prefetch = [&](int it, int buf) {
        const int k0 = it * BK;
        const float* Ap; int ka;
        if (CONCAT && k0 >= Ksplit) { Ap = Ab1; ka = k0 - Ksplit; }
        else                        { Ap = Ab0; ka = k0; }
        const uint32_t sa = sA_base + (uint32_t)buf * (BM * SA * 4);
        const float* s0 = Ap + (long)(m0 + ar) * lda + ka + akq;
        cp16(sa + (uint32_t)(ar * SA + akq) * 4, s0);
        cp16(sa + (uint32_t)((ar + 64) * SA + akq) * 4, s0 + 64 * lda);
        const uint32_t sb = sB_base + (uint32_t)buf * (1280 * 4);
        if (BKC) {
            cp16(sb + (uint32_t)(ar * SBT + akq) * 4,
                 Bb + (long)(n0 + ar) * ldb + k0 + akq);
        } else {
            cp16(sb + (uint32_t)(bkr * SBN + bnq) * 4,
                 Bb + (long)(k0 + bkr) * ldb + n0 + bnq);
        }
    };

    prefetch(0, 0);
    cp_commit();

    for (int it = 0; it < niter; it++) {
        const int buf = it & 1;
        if (it + 1 < niter) prefetch(it + 1, buf ^ 1);
        cp_commit();
        cp_wait1();
        __syncthreads();

        const float* as = &As[buf][0];
        const float* bs = &Bs[buf][0];

        #pragma unroll
        for (int kc = 0; kc < BK; kc += 8) {
            // A fragments (m16n8k8.row layout), split into hi/lo tf32
            uint32_t ah[2][4], al[2][4];
            #pragma unroll
            for (int i = 0; i < 2; i++) {
                const int r0 = wm + i * 16 + g;
                split2(as[r0 * SA + kc + t],           ah[i][0], al[i][0]);
                split2(as[(r0 + 8) * SA + kc + t],     ah[i][1], al[i][1]);
                split2(as[r0 * SA + kc + t + 4],       ah[i][2], al[i][2]);
                split2(as[(r0 + 8) * SA + kc + t + 4], ah[i][3], al[i][3]);
            }
            // B fragments
            uint32_t bh[4][2], bl[4][2];
            #pragma unroll
            for (int j = 0; j < 4; j++) {
                float f0, f1;
                if (BKC) {
                    const int n = wn + j * 8 + g;
                    f0 = bs[n * SBT + kc + t];
                    f1 = bs[n * SBT + kc + t + 4];
                } else {
                    const int n = wn + j * 8 + g;
                    f0 = bs[(kc + t) * SBN + n];
                    f1 = bs[(kc + t + 4) * SBN + n];
                }
                split2(f0, bh[j][0], bl[j][0]);
                split2(f1, bh[j][1], bl[j][1]);
            }
            // 3xTF32: D += Ah*Bh + Al*Bh + Ah*Bl
            #pragma unroll
            for (int i = 0; i < 2; i++)
                #pragma unroll
                for (int j = 0; j < 4; j++) {
                    mma8(acc[i][j], ah[i], bh[j]);
                    mma8(acc[i][j], al[i], bh[j]);
                    mma8(acc[i][j], ah[i], bl[j]);
                }
        }
        __syncthreads();
    }

    // epilogue: c0(g,2t) c1(g,2t+1) c2(g+8,2t) c3(g+8,2t+1)
    #pragma unroll
    for (int i = 0; i < 2; i++) {
        const int r0 = m0 + wm + i * 16 + g;
        #pragma unroll
        for (int j = 0; j < 4; j++) {
            const int cc = n0 + wn + j * 8 + t * 2;
            float d0 = acc[i][j][0], d1 = acc[i][j][1];
            float d2 = acc[i][j][2], d3 = acc[i][j][3];
            if (TANH) { d0 = tanhf(d0); d1 = tanhf(d1); d2 = tanhf(d2); d3 = tanhf(d3); }
            *(float2*)&Cb[(long)r0 * ldc + cc]       = make_float2(d0, d1);
            *(float2*)&Cb[(long)(r0 + 8) * ldc + cc] = make_float2(d2, d3);
        }
    }
}

// ---------------------------------------------------------------------------
// In-place softmax over rows of 2048 (one block per row, 256 threads x 8)
// ---------------------------------------------------------------------------
__global__ __launch_bounds__(256)
void softmax2048_kernel(float* __restrict__ S)
{
    float* row = S + (long)blockIdx.x * 2048;
    const int t = threadIdx.x;
    __shared__ float sred[8];

    float v[8];
    float mx = -3.402823466e38f;
    #pragma unroll
    for (int j = 0; j < 8; j++) {
        v[j] = row[t + j * 256];
        mx = fmaxf(mx, v[j]);
    }
    #pragma unroll
    for (int o = 16; o > 0; o >>= 1)
        mx = fmaxf(mx, __shfl_xor_sync(0xffffffffu, mx, o));
    if ((t & 31) == 0) sred[t >> 5] = mx;
    __syncthreads();
    mx = sred[0];
    #pragma unroll
    for (int w = 1; w < 8; w++) mx = fmaxf(mx, sred[w]);

    float s = 0.f;
    #pragma unroll
    for (int j = 0; j < 8; j++) {
        v[j] = expf(v[j] - mx);
        s += v[j];
    }
    #pragma unroll
    for (int o = 16; o > 0; o >>= 1)
        s += __shfl_xor_sync(0xffffffffu, s, o);
    __syncthreads();
    if ((t & 31) == 0) sred[t >> 5] = s;
    __syncthreads();
    s = 0.f;
    #pragma unroll
    for (int w = 0; w < 8; w++) s += sred[w];

    float inv = 1.f / s;
    #pragma unroll
    for (int j = 0; j < 8; j++)
        row[t + j * 256] = v[j] * inv;
}

// ---------------------------------------------------------------------------
extern "C" void kernel_launch(void* const* d_in, const int* in_sizes, int n_in,
                              void* d_out, int out_size)
{
    (void)in_sizes; (void)n_in; (void)out_size;
    const float* q     = (const float*)d_in[0];   // [QL, B, DIM]
    const float* c     = (const float*)d_in[1];   // [CL, B, DIM]
    const float* W_in  = (const float*)d_in[2];   // [DIM, DIM]
    const float* W_out = (const float*)d_in[3];   // [DIM, 2*DIM]

    float* out   = (float*)d_out;                       // [QL, B, DIM]
    float* score = out + (size_t)QL * BATCH * DIM;      // [B, QL, CL]

    float* qb  = nullptr;
    float* ctx = nullptr;
    cudaGetSymbolAddress((void**)&qb,  g_qb);
    cudaGetSymbolAddress((void**)&ctx, g_ctx);

    const long sQB = (long)QL * DIM;
    const long sSC = (long)QL * CL;

    // Stage 1: qb[b,q,e] = sum_d q[q,b,d] * W_in[e,d]
    {
        dim3 grid(DIM / BN, QL / BM, BATCH);
        gemm3t_kernel<false, false, true><<<grid, 256>>>(
            q, nullptr, (long)BATCH * DIM, DIM,
            W_in, DIM, 0,
            qb, DIM, sQB,
            DIM, 0);
    }

    // Stage 2: raw score[b,q,k] = sum_d qb[b,q,d] * c[k,b,d]
    {
        dim3 grid(CL / BN, QL / BM, BATCH);
        gemm3t_kernel<false, false, true><<<grid, 256>>>(
            qb, nullptr, DIM, sQB,
            c, (long)BATCH * DIM, DIM,
            score, CL, sSC,
            DIM, 0);
    }

    // Stage 3: softmax in place over last dim (CL=2048)
    softmax2048_kernel<<<BATCH * QL, 256>>>(score);

    // Stage 4: ctx[b,q,d] = sum_k score[b,q,k] * c[k,b,d]   (B is n-contiguous)
    {
        dim3 grid(DIM / BN, QL / BM, BATCH);
        gemm3t_kernel<false, false, false><<<grid, 256>>>(
            score, nullptr, CL, sSC,
            c, (long)BATCH * DIM, DIM,
            ctx, DIM, sQB,
            CL, 0);
    }

    // Stage 5: out[q,b,d] = tanh( sum_f [ctx|qb][b,q,f] * W_out[d,f] )
    {
        dim3 grid(DIM / BN, QL / BM, BATCH);
        gemm3t_kernel<true, true, true><<<grid, 256>>>(
            ctx, qb, DIM, sQB,
            W_out, 2 * DIM, 0,
            out, (long)BATCH * DIM, DIM,
            2 * DIM, DIM);
    }
}